// round 15
// baseline (speedup 1.0000x reference)
#include <cuda_runtime.h>

// Problem constants
#define BB      2048
#define NN      32
#define BN      65536      // B*N rows
#define DD      6
#define OBSD    17
#define HH      256
#define NSTEPS  10

#define MLP_ROWS  64                    // rows per CTA
#define MLP_GRID  (BN / MLP_ROWS)       // 1024
#define SMEM_FLOATS (16384 + 16384 + 8192 + 3072 + 1536 + 256)
#define SMEM_BYTES  (SMEM_FLOATS * 4)   // 183296 B

// Persistent device scratch (allocation-free rule: __device__ globals)
__device__ float g_a[BN * DD];
__device__ float g_score[BN * DD];
__device__ float g_logp[BN];
__device__ float g_W2T[HH * HH];

// ---------------- f32x2 packed math helpers (sm_100+) ----------------
static __device__ __forceinline__ unsigned long long pack2(float lo, float hi) {
    unsigned long long r;
    asm("mov.b64 %0, {%1, %2};" : "=l"(r) : "f"(lo), "f"(hi));
    return r;
}
static __device__ __forceinline__ void unpack2(unsigned long long v, float &lo, float &hi) {
    asm("mov.b64 {%0, %1}, %2;" : "=f"(lo), "=f"(hi) : "l"(v));
}
static __device__ __forceinline__ unsigned long long fma2(unsigned long long a,
                                                          unsigned long long b,
                                                          unsigned long long c) {
    unsigned long long d;
    asm("fma.rn.f32x2 %0, %1, %2, %3;" : "=l"(d) : "l"(a), "l"(b), "l"(c));
    return d;
}

// ---------------- small utility kernels ----------------
__global__ void transpose_w2_kernel(const float* __restrict__ W2) {
    int j = blockIdx.x;      // 256 blocks
    int k = threadIdx.x;     // 256 threads
    g_W2T[j * HH + k] = W2[k * HH + j];
}

__global__ void init_kernel(const float* __restrict__ a) {
    int idx = blockIdx.x * blockDim.x + threadIdx.x;
    if (idx < BN * DD) g_a[idx] = a[idx];
    if (idx < BN)      g_logp[idx] = 0.0f;
}

__global__ void writeout_kernel(float* __restrict__ out, int out_size) {
    int idx = blockIdx.x * blockDim.x + threadIdx.x;
    if (idx >= out_size) return;
    if (idx < BN * DD)            out[idx] = g_a[idx];
    else if (idx < BN * DD + BN)  out[idx] = g_logp[idx - BN * DD];
}

// ---------------- fused MLP forward+backward (score) ----------------
// One CTA = 64 rows. Warp w owns rows [8w, 8w+8) as 4 row-pairs packed f32x2.
// Phase 1: z1/h1 (K=23). Phase 2: z2 = h1@W2 -> dz2 = W3*(z2>0).
// Phase 3: dh1 = dz2@W2^T; dz1 = dh1*(z1>0); score = dz1@W1a^T (D=6).
__global__ __launch_bounds__(256, 1)
void mlp_score_kernel(const float* __restrict__ obs,
                      const float* __restrict__ W1,
                      const float* __restrict__ b1,
                      const float* __restrict__ W2,
                      const float* __restrict__ b2,
                      const float* __restrict__ W3) {
    extern __shared__ float smem[];
    float* h1p  = smem;             // 32 pairs x 256 x 2   = 16384 f
    float* dz2p = h1p + 16384;      // 16384 f
    float* wtd  = dz2p + 16384;     // 16 x 256 x 2 (dup)   = 8192 f
    float* w1ad = wtd + 8192;       // 6 x 256 x 2 (dup)    = 3072 f
    float* xs   = w1ad + 3072;      // 64 x 24              = 1536 f
    float* w3s  = xs + 1536;        // 256 f

    unsigned long long* h1u  = reinterpret_cast<unsigned long long*>(h1p);
    unsigned long long* dz2u = reinterpret_cast<unsigned long long*>(dz2p);
    unsigned long long* wtdu = reinterpret_cast<unsigned long long*>(wtd);
    unsigned long long* w1au = reinterpret_cast<unsigned long long*>(w1ad);

    const int t    = threadIdx.x;
    const int lane = t & 31;
    const int w    = t >> 5;          // 8 warps
    const int R0   = blockIdx.x * MLP_ROWS;

    // ---- stage inputs ----
    for (int idx = t; idx < MLP_ROWS * OBSD; idx += 256)
        xs[(idx / OBSD) * 24 + (idx % OBSD)] = obs[R0 * OBSD + idx];
    for (int idx = t; idx < MLP_ROWS * DD; idx += 256)
        xs[(idx / DD) * 24 + OBSD + (idx % DD)] = g_a[R0 * DD + idx];
    for (int idx = t; idx < DD * HH; idx += 256) {
        float v = W1[OBSD * HH + idx];   // rows 17..22 of W1
        w1au[idx] = pack2(v, v);
    }
    if (t < HH) w3s[t] = W3[t];
    __syncthreads();

    // ---- phase 1: h1 = relu(x @ W1 + b1), rows 8w..8w+7, cols lane+32*jj ----
    {
        float acc[8][8];
        float bj[8];
        #pragma unroll
        for (int jj = 0; jj < 8; jj++) bj[jj] = b1[lane + 32 * jj];
        #pragma unroll
        for (int rr = 0; rr < 8; rr++)
            #pragma unroll
            for (int jj = 0; jj < 8; jj++) acc[rr][jj] = bj[jj];
        for (int i = 0; i < OBSD + DD; i++) {
            float wv[8];
            #pragma unroll
            for (int jj = 0; jj < 8; jj++) wv[jj] = W1[i * HH + lane + 32 * jj];
            #pragma unroll
            for (int rr = 0; rr < 8; rr++) {
                float xv = xs[(8 * w + rr) * 24 + i];
                #pragma unroll
                for (int jj = 0; jj < 8; jj++) acc[rr][jj] = fmaf(xv, wv[jj], acc[rr][jj]);
            }
        }
        #pragma unroll
        for (int rr = 0; rr < 8; rr++) {
            int r = 8 * w + rr;
            #pragma unroll
            for (int jj = 0; jj < 8; jj++) {
                int j = lane + 32 * jj;
                h1p[(r >> 1) * 512 + j * 2 + (r & 1)] = fmaxf(acc[rr][jj], 0.0f);
            }
        }
    }
    __syncthreads();

    // ---- phase 2: z2 = h1 @ W2 + b2 ; dz2 = (z2>0) * W3[j] ----
    {
        unsigned long long acc2[4][8];
        #pragma unroll
        for (int jj = 0; jj < 8; jj++) {
            float bv = b2[lane + 32 * jj];
            unsigned long long bb = pack2(bv, bv);
            #pragma unroll
            for (int pp = 0; pp < 4; pp++) acc2[pp][jj] = bb;
        }
        for (int c = 0; c < 16; c++) {
            __syncthreads();
            #pragma unroll
            for (int q = 0; q < 16; q++) {
                float v = W2[(c * 16 + q) * HH + t];
                wtdu[q * 256 + t] = pack2(v, v);
            }
            __syncthreads();
            #pragma unroll
            for (int kk = 0; kk < 16; kk++) {
                unsigned long long wv[8];
                #pragma unroll
                for (int jj = 0; jj < 8; jj++) wv[jj] = wtdu[kk * 256 + lane + 32 * jj];
                #pragma unroll
                for (int pp = 0; pp < 4; pp++) {
                    unsigned long long hv = h1u[(4 * w + pp) * 256 + c * 16 + kk];
                    #pragma unroll
                    for (int jj = 0; jj < 8; jj++)
                        acc2[pp][jj] = fma2(hv, wv[jj], acc2[pp][jj]);
                }
            }
        }
        #pragma unroll
        for (int pp = 0; pp < 4; pp++)
            #pragma unroll
            for (int jj = 0; jj < 8; jj++) {
                int j = lane + 32 * jj;
                float zlo, zhi;
                unpack2(acc2[pp][jj], zlo, zhi);
                float wv3 = w3s[j];
                dz2u[(4 * w + pp) * 256 + j] =
                    pack2(zlo > 0.0f ? wv3 : 0.0f, zhi > 0.0f ? wv3 : 0.0f);
            }
    }

    // ---- phase 3: dh1 = dz2 @ W2^T ; dz1 = dh1 * (h1>0) ; score = dz1 @ W1a^T ----
    {
        unsigned long long acc2[4][8];
        #pragma unroll
        for (int pp = 0; pp < 4; pp++)
            #pragma unroll
            for (int kk = 0; kk < 8; kk++) acc2[pp][kk] = 0ull;

        for (int c = 0; c < 16; c++) {
            __syncthreads();   // protects wtd reuse across phases/chunks
            #pragma unroll
            for (int q = 0; q < 16; q++) {
                float v = g_W2T[(c * 16 + q) * HH + t];
                wtdu[q * 256 + t] = pack2(v, v);
            }
            __syncthreads();
            #pragma unroll
            for (int jr = 0; jr < 16; jr++) {
                unsigned long long wv[8];
                #pragma unroll
                for (int kk = 0; kk < 8; kk++) wv[kk] = wtdu[jr * 256 + lane + 32 * kk];
                #pragma unroll
                for (int pp = 0; pp < 4; pp++) {
                    unsigned long long dzv = dz2u[(4 * w + pp) * 256 + c * 16 + jr];
                    #pragma unroll
                    for (int kk = 0; kk < 8; kk++)
                        acc2[pp][kk] = fma2(dzv, wv[kk], acc2[pp][kk]);
                }
            }
        }

        unsigned long long sacc[4][6];
        #pragma unroll
        for (int pp = 0; pp < 4; pp++)
            #pragma unroll
            for (int d = 0; d < 6; d++) sacc[pp][d] = 0ull;

        #pragma unroll
        for (int pp = 0; pp < 4; pp++) {
            #pragma unroll
            for (int kk = 0; kk < 8; kk++) {
                int k = lane + 32 * kk;
                float dlo, dhi, hlo, hhi;
                unpack2(acc2[pp][kk], dlo, dhi);
                unpack2(h1u[(4 * w + pp) * 256 + k], hlo, hhi);
                dlo = hlo > 0.0f ? dlo : 0.0f;
                dhi = hhi > 0.0f ? dhi : 0.0f;
                unsigned long long dz1 = pack2(dlo, dhi);
                #pragma unroll
                for (int d = 0; d < 6; d++)
                    sacc[pp][d] = fma2(dz1, w1au[d * 256 + k], sacc[pp][d]);
            }
        }

        float slo[24], shi[24];
        #pragma unroll
        for (int pp = 0; pp < 4; pp++)
            #pragma unroll
            for (int d = 0; d < 6; d++) unpack2(sacc[pp][d], slo[pp * 6 + d], shi[pp * 6 + d]);

        #pragma unroll
        for (int off = 16; off > 0; off >>= 1) {
            #pragma unroll
            for (int q = 0; q < 24; q++) {
                slo[q] += __shfl_xor_sync(0xffffffffu, slo[q], off);
                shi[q] += __shfl_xor_sync(0xffffffffu, shi[q], off);
            }
        }
        if (lane == 0) {
            #pragma unroll
            for (int pp = 0; pp < 4; pp++) {
                int r0 = R0 + 8 * w + 2 * pp;
                #pragma unroll
                for (int d = 0; d < 6; d++) {
                    g_score[r0 * DD + d]       = slo[pp * 6 + d];
                    g_score[(r0 + 1) * DD + d] = shi[pp * 6 + d];
                }
            }
        }
    }
}

// ---------------- SVGD / RBF update: one CTA (1024 thr) per batch ----------------
__global__ __launch_bounds__(1024)
void svgd_kernel() {
    const int b   = blockIdx.x;
    const int tid = threadIdx.x;
    const int i   = tid >> 5;     // particle i (warp)
    const int j   = tid & 31;     // particle j (lane)

    __shared__ float xsm[NN][DD];
    __shared__ float ssm[NN][DD];
    __shared__ float sd[NN * NN];

    if (tid < NN * DD) {
        xsm[tid / DD][tid % DD] = g_a[b * NN * DD + tid];
    } else if (tid < 2 * NN * DD) {
        int q = tid - NN * DD;
        ssm[q / DD][q % DD] = g_score[b * NN * DD + q];
    }
    __syncthreads();

    float diff[DD];
    float dsq = 0.0f;
    #pragma unroll
    for (int d = 0; d < DD; d++) {
        float df = xsm[i][d] - xsm[j][d];
        diff[d] = df;
        dsq += df * df;
    }
    sd[tid] = dsq;
    __syncthreads();

    // bitonic sort of 1024 distances (ascending), exact median semantics
    for (int k = 2; k <= 1024; k <<= 1) {
        for (int m = k >> 1; m > 0; m >>= 1) {
            int ixj = tid ^ m;
            if (ixj > tid) {
                float v0 = sd[tid], v1 = sd[ixj];
                bool asc = ((tid & k) == 0);
                bool swap = asc ? (v0 > v1) : (v0 < v1);
                if (swap) { sd[tid] = v1; sd[ixj] = v0; }
            }
            __syncthreads();
        }
    }
    float med = sd[(NN * NN - 1) / 2];   // index 511
    const float LOG_NP1 = 3.4965076f;    // float32(log(33))
    float h     = med / (2.0f * LOG_NP1);
    float gamma = 1.0f / (1e-8f + 2.0f * h);

    float Kv   = expf(-gamma * dsq);
    float coef = -2.0f * gamma * Kv;     // Kgrad_d = coef * diff_d

    float phi[DD];
    float l4 = 0.0f;
    #pragma unroll
    for (int d = 0; d < DD; d++) {
        float kg = coef * diff[d];
        float sv = ssm[j][d];
        phi[d] = Kv * sv - kg;           // K*s - Kgrad.sum contribution
        l4 += kg * sv;
    }
    float l5 = 2.0f * gamma * dsq * Kv - (float)DD * Kv;

    // reduce over j (lanes)
    #pragma unroll
    for (int off = 16; off > 0; off >>= 1) {
        #pragma unroll
        for (int d = 0; d < DD; d++)
            phi[d] += __shfl_xor_sync(0xffffffffu, phi[d], off);
        l4 += __shfl_xor_sync(0xffffffffu, l4, off);
        l5 += __shfl_xor_sync(0xffffffffu, l5, off);
    }

    if (j == 0) {
        int row = b * NN + i;
        #pragma unroll
        for (int d = 0; d < DD; d++) {
            float an = xsm[i][d] + 0.1f * (phi[d] * (1.0f / (float)NN));
            an = fminf(fmaxf(an, -1.0f), 1.0f);
            g_a[row * DD + d] = an;
        }
        float line4 = l4 * (1.0f / (float)NN);
        float line5 = -2.0f * gamma * (l5 * (1.0f / (float)NN));
        g_logp[row] = g_logp[row] - 0.1f * (line4 + line5);
    }
}

// ---------------- launcher ----------------
extern "C" void kernel_launch(void* const* d_in, const int* in_sizes, int n_in,
                              void* d_out, int out_size) {
    const float* obs = (const float*)d_in[0];
    const float* a   = (const float*)d_in[1];
    const float* W1  = (const float*)d_in[2];
    const float* b1  = (const float*)d_in[3];
    const float* W2  = (const float*)d_in[4];
    const float* b2  = (const float*)d_in[5];
    const float* W3  = (const float*)d_in[6];
    float* out = (float*)d_out;

    cudaFuncSetAttribute(mlp_score_kernel,
                         cudaFuncAttributeMaxDynamicSharedMemorySize, SMEM_BYTES);

    transpose_w2_kernel<<<HH, HH>>>(W2);
    init_kernel<<<(BN * DD + 255) / 256, 256>>>(a);

    for (int s = 0; s < NSTEPS; s++) {
        mlp_score_kernel<<<MLP_GRID, 256, SMEM_BYTES>>>(obs, W1, b1, W2, b2, W3);
        svgd_kernel<<<BB, 1024>>>();
    }

    int total = BN * DD + BN;  // a (393216) then logp (65536)
    int n = (out_size < total) ? out_size : total;
    writeout_kernel<<<(n + 255) / 256, 256>>>(out, n);
}

// round 16
// speedup vs baseline: 1.0022x; 1.0022x over previous
#include <cuda_runtime.h>

// Problem constants
#define BB      2048
#define NN      32
#define BN      65536      // B*N rows
#define DD      6
#define OBSD    17
#define HH      256
#define NSTEPS  10

#define MLP_ROWS  64                    // rows per CTA
#define MLP_GRID  (BN / MLP_ROWS)       // 1024
#define SMEM_FLOATS (16384 + 16384 + 8192 + 3072 + 1536 + 256)
#define SMEM_BYTES  (SMEM_FLOATS * 4)   // 183296 B

// Persistent device scratch (allocation-free rule: __device__ globals)
__device__ float g_a[BN * DD];
__device__ float g_score[BN * DD];
__device__ float g_logp[BN];
__device__ float g_W2T[HH * HH];

// ---------------- f32x2 packed math helpers (sm_100+) ----------------
static __device__ __forceinline__ unsigned long long pack2(float lo, float hi) {
    unsigned long long r;
    asm("mov.b64 %0, {%1, %2};" : "=l"(r) : "f"(lo), "f"(hi));
    return r;
}
static __device__ __forceinline__ void unpack2(unsigned long long v, float &lo, float &hi) {
    asm("mov.b64 {%0, %1}, %2;" : "=f"(lo), "=f"(hi) : "l"(v));
}
static __device__ __forceinline__ unsigned long long fma2(unsigned long long a,
                                                          unsigned long long b,
                                                          unsigned long long c) {
    unsigned long long d;
    asm("fma.rn.f32x2 %0, %1, %2, %3;" : "=l"(d) : "l"(a), "l"(b), "l"(c));
    return d;
}

// ---------------- small utility kernels ----------------
__global__ void transpose_w2_kernel(const float* __restrict__ W2) {
    int j = blockIdx.x;      // 256 blocks
    int k = threadIdx.x;     // 256 threads
    g_W2T[j * HH + k] = W2[k * HH + j];
}

__global__ void init_kernel(const float* __restrict__ a) {
    int idx = blockIdx.x * blockDim.x + threadIdx.x;
    if (idx < BN * DD) g_a[idx] = a[idx];
    if (idx < BN)      g_logp[idx] = 0.0f;
}

__global__ void writeout_kernel(float* __restrict__ out, int out_size) {
    int idx = blockIdx.x * blockDim.x + threadIdx.x;
    if (idx >= out_size) return;
    if (idx < BN * DD)            out[idx] = g_a[idx];
    else if (idx < BN * DD + BN)  out[idx] = g_logp[idx - BN * DD];
}

// ---------------- fused MLP forward+backward (score) ----------------
// One CTA = 64 rows. Warp w owns rows [8w, 8w+8) as 4 row-pairs packed f32x2.
// Phase 1: z1/h1 (K=23). Phase 2: z2 = h1@W2 -> dz2 = W3*(z2>0).
// Phase 3: dh1 = dz2@W2^T; dz1 = dh1*(z1>0); score = dz1@W1a^T (D=6).
__global__ __launch_bounds__(256, 1)
void mlp_score_kernel(const float* __restrict__ obs,
                      const float* __restrict__ W1,
                      const float* __restrict__ b1,
                      const float* __restrict__ W2,
                      const float* __restrict__ b2,
                      const float* __restrict__ W3) {
    extern __shared__ float smem[];
    float* h1p  = smem;             // 32 pairs x 256 x 2   = 16384 f
    float* dz2p = h1p + 16384;      // 16384 f
    float* wtd  = dz2p + 16384;     // 16 x 256 x 2 (dup)   = 8192 f
    float* w1ad = wtd + 8192;       // 6 x 256 x 2 (dup)    = 3072 f
    float* xs   = w1ad + 3072;      // 64 x 24              = 1536 f
    float* w3s  = xs + 1536;        // 256 f

    unsigned long long* h1u  = reinterpret_cast<unsigned long long*>(h1p);
    unsigned long long* dz2u = reinterpret_cast<unsigned long long*>(dz2p);
    unsigned long long* wtdu = reinterpret_cast<unsigned long long*>(wtd);
    unsigned long long* w1au = reinterpret_cast<unsigned long long*>(w1ad);

    const int t    = threadIdx.x;
    const int lane = t & 31;
    const int w    = t >> 5;          // 8 warps
    const int R0   = blockIdx.x * MLP_ROWS;

    // ---- stage inputs ----
    for (int idx = t; idx < MLP_ROWS * OBSD; idx += 256)
        xs[(idx / OBSD) * 24 + (idx % OBSD)] = obs[R0 * OBSD + idx];
    for (int idx = t; idx < MLP_ROWS * DD; idx += 256)
        xs[(idx / DD) * 24 + OBSD + (idx % DD)] = g_a[R0 * DD + idx];
    for (int idx = t; idx < DD * HH; idx += 256) {
        float v = W1[OBSD * HH + idx];   // rows 17..22 of W1
        w1au[idx] = pack2(v, v);
    }
    if (t < HH) w3s[t] = W3[t];
    __syncthreads();

    // ---- phase 1: h1 = relu(x @ W1 + b1), rows 8w..8w+7, cols lane+32*jj ----
    {
        float acc[8][8];
        float bj[8];
        #pragma unroll
        for (int jj = 0; jj < 8; jj++) bj[jj] = b1[lane + 32 * jj];
        #pragma unroll
        for (int rr = 0; rr < 8; rr++)
            #pragma unroll
            for (int jj = 0; jj < 8; jj++) acc[rr][jj] = bj[jj];
        for (int i = 0; i < OBSD + DD; i++) {
            float wv[8];
            #pragma unroll
            for (int jj = 0; jj < 8; jj++) wv[jj] = W1[i * HH + lane + 32 * jj];
            #pragma unroll
            for (int rr = 0; rr < 8; rr++) {
                float xv = xs[(8 * w + rr) * 24 + i];
                #pragma unroll
                for (int jj = 0; jj < 8; jj++) acc[rr][jj] = fmaf(xv, wv[jj], acc[rr][jj]);
            }
        }
        #pragma unroll
        for (int rr = 0; rr < 8; rr++) {
            int r = 8 * w + rr;
            #pragma unroll
            for (int jj = 0; jj < 8; jj++) {
                int j = lane + 32 * jj;
                h1p[(r >> 1) * 512 + j * 2 + (r & 1)] = fmaxf(acc[rr][jj], 0.0f);
            }
        }
    }
    __syncthreads();

    // ---- phase 2: z2 = h1 @ W2 + b2 ; dz2 = (z2>0) * W3[j] ----
    {
        unsigned long long acc2[4][8];
        #pragma unroll
        for (int jj = 0; jj < 8; jj++) {
            float bv = b2[lane + 32 * jj];
            unsigned long long bb = pack2(bv, bv);
            #pragma unroll
            for (int pp = 0; pp < 4; pp++) acc2[pp][jj] = bb;
        }
        for (int c = 0; c < 16; c++) {
            __syncthreads();
            #pragma unroll
            for (int q = 0; q < 16; q++) {
                float v = W2[(c * 16 + q) * HH + t];
                wtdu[q * 256 + t] = pack2(v, v);
            }
            __syncthreads();
            #pragma unroll
            for (int kk = 0; kk < 16; kk++) {
                unsigned long long wv[8];
                #pragma unroll
                for (int jj = 0; jj < 8; jj++) wv[jj] = wtdu[kk * 256 + lane + 32 * jj];
                #pragma unroll
                for (int pp = 0; pp < 4; pp++) {
                    unsigned long long hv = h1u[(4 * w + pp) * 256 + c * 16 + kk];
                    #pragma unroll
                    for (int jj = 0; jj < 8; jj++)
                        acc2[pp][jj] = fma2(hv, wv[jj], acc2[pp][jj]);
                }
            }
        }
        #pragma unroll
        for (int pp = 0; pp < 4; pp++)
            #pragma unroll
            for (int jj = 0; jj < 8; jj++) {
                int j = lane + 32 * jj;
                float zlo, zhi;
                unpack2(acc2[pp][jj], zlo, zhi);
                float wv3 = w3s[j];
                dz2u[(4 * w + pp) * 256 + j] =
                    pack2(zlo > 0.0f ? wv3 : 0.0f, zhi > 0.0f ? wv3 : 0.0f);
            }
    }

    // ---- phase 3: dh1 = dz2 @ W2^T ; dz1 = dh1 * (h1>0) ; score = dz1 @ W1a^T ----
    {
        unsigned long long acc2[4][8];
        #pragma unroll
        for (int pp = 0; pp < 4; pp++)
            #pragma unroll
            for (int kk = 0; kk < 8; kk++) acc2[pp][kk] = 0ull;

        for (int c = 0; c < 16; c++) {
            __syncthreads();   // protects wtd reuse across phases/chunks
            #pragma unroll
            for (int q = 0; q < 16; q++) {
                float v = g_W2T[(c * 16 + q) * HH + t];
                wtdu[q * 256 + t] = pack2(v, v);
            }
            __syncthreads();
            #pragma unroll
            for (int jr = 0; jr < 16; jr++) {
                unsigned long long wv[8];
                #pragma unroll
                for (int kk = 0; kk < 8; kk++) wv[kk] = wtdu[jr * 256 + lane + 32 * kk];
                #pragma unroll
                for (int pp = 0; pp < 4; pp++) {
                    unsigned long long dzv = dz2u[(4 * w + pp) * 256 + c * 16 + jr];
                    #pragma unroll
                    for (int kk = 0; kk < 8; kk++)
                        acc2[pp][kk] = fma2(dzv, wv[kk], acc2[pp][kk]);
                }
            }
        }

        unsigned long long sacc[4][6];
        #pragma unroll
        for (int pp = 0; pp < 4; pp++)
            #pragma unroll
            for (int d = 0; d < 6; d++) sacc[pp][d] = 0ull;

        #pragma unroll
        for (int pp = 0; pp < 4; pp++) {
            #pragma unroll
            for (int kk = 0; kk < 8; kk++) {
                int k = lane + 32 * kk;
                float dlo, dhi, hlo, hhi;
                unpack2(acc2[pp][kk], dlo, dhi);
                unpack2(h1u[(4 * w + pp) * 256 + k], hlo, hhi);
                dlo = hlo > 0.0f ? dlo : 0.0f;
                dhi = hhi > 0.0f ? dhi : 0.0f;
                unsigned long long dz1 = pack2(dlo, dhi);
                #pragma unroll
                for (int d = 0; d < 6; d++)
                    sacc[pp][d] = fma2(dz1, w1au[d * 256 + k], sacc[pp][d]);
            }
        }

        float slo[24], shi[24];
        #pragma unroll
        for (int pp = 0; pp < 4; pp++)
            #pragma unroll
            for (int d = 0; d < 6; d++) unpack2(sacc[pp][d], slo[pp * 6 + d], shi[pp * 6 + d]);

        #pragma unroll
        for (int off = 16; off > 0; off >>= 1) {
            #pragma unroll
            for (int q = 0; q < 24; q++) {
                slo[q] += __shfl_xor_sync(0xffffffffu, slo[q], off);
                shi[q] += __shfl_xor_sync(0xffffffffu, shi[q], off);
            }
        }
        if (lane == 0) {
            #pragma unroll
            for (int pp = 0; pp < 4; pp++) {
                int r0 = R0 + 8 * w + 2 * pp;
                #pragma unroll
                for (int d = 0; d < 6; d++) {
                    g_score[r0 * DD + d]       = slo[pp * 6 + d];
                    g_score[(r0 + 1) * DD + d] = shi[pp * 6 + d];
                }
            }
        }
    }
}

// ---------------- SVGD / RBF update: one CTA (1024 thr) per batch ----------------
__global__ __launch_bounds__(1024)
void svgd_kernel() {
    const int b   = blockIdx.x;
    const int tid = threadIdx.x;
    const int i   = tid >> 5;     // particle i (warp)
    const int j   = tid & 31;     // particle j (lane)

    __shared__ float xsm[NN][DD];
    __shared__ float ssm[NN][DD];
    __shared__ float sd[NN * NN];

    if (tid < NN * DD) {
        xsm[tid / DD][tid % DD] = g_a[b * NN * DD + tid];
    } else if (tid < 2 * NN * DD) {
        int q = tid - NN * DD;
        ssm[q / DD][q % DD] = g_score[b * NN * DD + q];
    }
    __syncthreads();

    float diff[DD];
    float dsq = 0.0f;
    #pragma unroll
    for (int d = 0; d < DD; d++) {
        float df = xsm[i][d] - xsm[j][d];
        diff[d] = df;
        dsq += df * df;
    }
    sd[tid] = dsq;
    __syncthreads();

    // bitonic sort of 1024 distances (ascending), exact median semantics
    for (int k = 2; k <= 1024; k <<= 1) {
        for (int m = k >> 1; m > 0; m >>= 1) {
            int ixj = tid ^ m;
            if (ixj > tid) {
                float v0 = sd[tid], v1 = sd[ixj];
                bool asc = ((tid & k) == 0);
                bool swap = asc ? (v0 > v1) : (v0 < v1);
                if (swap) { sd[tid] = v1; sd[ixj] = v0; }
            }
            __syncthreads();
        }
    }
    float med = sd[(NN * NN - 1) / 2];   // index 511
    const float LOG_NP1 = 3.4965076f;    // float32(log(33))
    float h     = med / (2.0f * LOG_NP1);
    float gamma = 1.0f / (1e-8f + 2.0f * h);

    float Kv   = expf(-gamma * dsq);
    float coef = -2.0f * gamma * Kv;     // Kgrad_d = coef * diff_d

    float phi[DD];
    float l4 = 0.0f;
    #pragma unroll
    for (int d = 0; d < DD; d++) {
        float kg = coef * diff[d];
        float sv = ssm[j][d];
        phi[d] = Kv * sv - kg;           // K*s - Kgrad.sum contribution
        l4 += kg * sv;
    }
    float l5 = 2.0f * gamma * dsq * Kv - (float)DD * Kv;

    // reduce over j (lanes)
    #pragma unroll
    for (int off = 16; off > 0; off >>= 1) {
        #pragma unroll
        for (int d = 0; d < DD; d++)
            phi[d] += __shfl_xor_sync(0xffffffffu, phi[d], off);
        l4 += __shfl_xor_sync(0xffffffffu, l4, off);
        l5 += __shfl_xor_sync(0xffffffffu, l5, off);
    }

    if (j == 0) {
        int row = b * NN + i;
        #pragma unroll
        for (int d = 0; d < DD; d++) {
            float an = xsm[i][d] + 0.1f * (phi[d] * (1.0f / (float)NN));
            an = fminf(fmaxf(an, -1.0f), 1.0f);
            g_a[row * DD + d] = an;
        }
        float line4 = l4 * (1.0f / (float)NN);
        float line5 = -2.0f * gamma * (l5 * (1.0f / (float)NN));
        g_logp[row] = g_logp[row] - 0.1f * (line4 + line5);
    }
}

// ---------------- launcher ----------------
extern "C" void kernel_launch(void* const* d_in, const int* in_sizes, int n_in,
                              void* d_out, int out_size) {
    const float* obs = (const float*)d_in[0];
    const float* a   = (const float*)d_in[1];
    const float* W1  = (const float*)d_in[2];
    const float* b1  = (const float*)d_in[3];
    const float* W2  = (const float*)d_in[4];
    const float* b2  = (const float*)d_in[5];
    const float* W3  = (const float*)d_in[6];
    float* out = (float*)d_out;

    cudaFuncSetAttribute(mlp_score_kernel,
                         cudaFuncAttributeMaxDynamicSharedMemorySize, SMEM_BYTES);

    transpose_w2_kernel<<<HH, HH>>>(W2);
    init_kernel<<<(BN * DD + 255) / 256, 256>>>(a);

    for (int s = 0; s < NSTEPS; s++) {
        mlp_score_kernel<<<MLP_GRID, 256, SMEM_BYTES>>>(obs, W1, b1, W2, b2, W3);
        svgd_kernel<<<BB, 1024>>>();
    }

    int total = BN * DD + BN;  // a (393216) then logp (65536)
    int n = (out_size < total) ? out_size : total;
    writeout_kernel<<<(n + 255) / 256, 256>>>(out, n);
}

// round 17
// speedup vs baseline: 1.0027x; 1.0006x over previous
#include <cuda_runtime.h>

// Problem constants
#define BB      2048
#define NN      32
#define BN      65536      // B*N rows
#define DD      6
#define OBSD    17
#define HH      256
#define NSTEPS  10

#define MLP_ROWS  64                    // rows per CTA
#define MLP_GRID  (BN / MLP_ROWS)       // 1024
#define SMEM_FLOATS (16384 + 16384 + 8192 + 3072 + 1536 + 256)
#define SMEM_BYTES  (SMEM_FLOATS * 4)   // 183296 B

// Persistent device scratch (allocation-free rule: __device__ globals)
__device__ float g_a[BN * DD];
__device__ float g_score[BN * DD];
__device__ float g_logp[BN];
__device__ float g_W2T[HH * HH];

// ---------------- f32x2 packed math helpers (sm_100+) ----------------
static __device__ __forceinline__ unsigned long long pack2(float lo, float hi) {
    unsigned long long r;
    asm("mov.b64 %0, {%1, %2};" : "=l"(r) : "f"(lo), "f"(hi));
    return r;
}
static __device__ __forceinline__ void unpack2(unsigned long long v, float &lo, float &hi) {
    asm("mov.b64 {%0, %1}, %2;" : "=f"(lo), "=f"(hi) : "l"(v));
}
static __device__ __forceinline__ unsigned long long fma2(unsigned long long a,
                                                          unsigned long long b,
                                                          unsigned long long c) {
    unsigned long long d;
    asm("fma.rn.f32x2 %0, %1, %2, %3;" : "=l"(d) : "l"(a), "l"(b), "l"(c));
    return d;
}

// ---------------- small utility kernels ----------------
__global__ void transpose_w2_kernel(const float* __restrict__ W2) {
    int j = blockIdx.x;      // 256 blocks
    int k = threadIdx.x;     // 256 threads
    g_W2T[j * HH + k] = W2[k * HH + j];
}

__global__ void init_kernel(const float* __restrict__ a) {
    int idx = blockIdx.x * blockDim.x + threadIdx.x;
    if (idx < BN * DD) g_a[idx] = a[idx];
    if (idx < BN)      g_logp[idx] = 0.0f;
}

__global__ void writeout_kernel(float* __restrict__ out, int out_size) {
    int idx = blockIdx.x * blockDim.x + threadIdx.x;
    if (idx >= out_size) return;
    if (idx < BN * DD)            out[idx] = g_a[idx];
    else if (idx < BN * DD + BN)  out[idx] = g_logp[idx - BN * DD];
}

// ---------------- fused MLP forward+backward (score) ----------------
// One CTA = 64 rows. Warp w owns rows [8w, 8w+8) as 4 row-pairs packed f32x2.
// Phase 1: z1/h1 (K=23). Phase 2: z2 = h1@W2 -> dz2 = W3*(z2>0).
// Phase 3: dh1 = dz2@W2^T; dz1 = dh1*(z1>0); score = dz1@W1a^T (D=6).
__global__ __launch_bounds__(256, 1)
void mlp_score_kernel(const float* __restrict__ obs,
                      const float* __restrict__ W1,
                      const float* __restrict__ b1,
                      const float* __restrict__ W2,
                      const float* __restrict__ b2,
                      const float* __restrict__ W3) {
    extern __shared__ float smem[];
    float* h1p  = smem;             // 32 pairs x 256 x 2   = 16384 f
    float* dz2p = h1p + 16384;      // 16384 f
    float* wtd  = dz2p + 16384;     // 16 x 256 x 2 (dup)   = 8192 f
    float* w1ad = wtd + 8192;       // 6 x 256 x 2 (dup)    = 3072 f
    float* xs   = w1ad + 3072;      // 64 x 24              = 1536 f
    float* w3s  = xs + 1536;        // 256 f

    unsigned long long* h1u  = reinterpret_cast<unsigned long long*>(h1p);
    unsigned long long* dz2u = reinterpret_cast<unsigned long long*>(dz2p);
    unsigned long long* wtdu = reinterpret_cast<unsigned long long*>(wtd);
    unsigned long long* w1au = reinterpret_cast<unsigned long long*>(w1ad);

    const int t    = threadIdx.x;
    const int lane = t & 31;
    const int w    = t >> 5;          // 8 warps
    const int R0   = blockIdx.x * MLP_ROWS;

    // ---- stage inputs ----
    for (int idx = t; idx < MLP_ROWS * OBSD; idx += 256)
        xs[(idx / OBSD) * 24 + (idx % OBSD)] = obs[R0 * OBSD + idx];
    for (int idx = t; idx < MLP_ROWS * DD; idx += 256)
        xs[(idx / DD) * 24 + OBSD + (idx % DD)] = g_a[R0 * DD + idx];
    for (int idx = t; idx < DD * HH; idx += 256) {
        float v = W1[OBSD * HH + idx];   // rows 17..22 of W1
        w1au[idx] = pack2(v, v);
    }
    if (t < HH) w3s[t] = W3[t];
    __syncthreads();

    // ---- phase 1: h1 = relu(x @ W1 + b1), rows 8w..8w+7, cols lane+32*jj ----
    {
        float acc[8][8];
        float bj[8];
        #pragma unroll
        for (int jj = 0; jj < 8; jj++) bj[jj] = b1[lane + 32 * jj];
        #pragma unroll
        for (int rr = 0; rr < 8; rr++)
            #pragma unroll
            for (int jj = 0; jj < 8; jj++) acc[rr][jj] = bj[jj];
        for (int i = 0; i < OBSD + DD; i++) {
            float wv[8];
            #pragma unroll
            for (int jj = 0; jj < 8; jj++) wv[jj] = W1[i * HH + lane + 32 * jj];
            #pragma unroll
            for (int rr = 0; rr < 8; rr++) {
                float xv = xs[(8 * w + rr) * 24 + i];
                #pragma unroll
                for (int jj = 0; jj < 8; jj++) acc[rr][jj] = fmaf(xv, wv[jj], acc[rr][jj]);
            }
        }
        #pragma unroll
        for (int rr = 0; rr < 8; rr++) {
            int r = 8 * w + rr;
            #pragma unroll
            for (int jj = 0; jj < 8; jj++) {
                int j = lane + 32 * jj;
                h1p[(r >> 1) * 512 + j * 2 + (r & 1)] = fmaxf(acc[rr][jj], 0.0f);
            }
        }
    }
    __syncthreads();

    // ---- phase 2: z2 = h1 @ W2 + b2 ; dz2 = (z2>0) * W3[j] ----
    {
        unsigned long long acc2[4][8];
        #pragma unroll
        for (int jj = 0; jj < 8; jj++) {
            float bv = b2[lane + 32 * jj];
            unsigned long long bb = pack2(bv, bv);
            #pragma unroll
            for (int pp = 0; pp < 4; pp++) acc2[pp][jj] = bb;
        }
        for (int c = 0; c < 16; c++) {
            __syncthreads();
            #pragma unroll
            for (int q = 0; q < 16; q++) {
                float v = W2[(c * 16 + q) * HH + t];
                wtdu[q * 256 + t] = pack2(v, v);
            }
            __syncthreads();
            #pragma unroll
            for (int kk = 0; kk < 16; kk++) {
                unsigned long long wv[8];
                #pragma unroll
                for (int jj = 0; jj < 8; jj++) wv[jj] = wtdu[kk * 256 + lane + 32 * jj];
                #pragma unroll
                for (int pp = 0; pp < 4; pp++) {
                    unsigned long long hv = h1u[(4 * w + pp) * 256 + c * 16 + kk];
                    #pragma unroll
                    for (int jj = 0; jj < 8; jj++)
                        acc2[pp][jj] = fma2(hv, wv[jj], acc2[pp][jj]);
                }
            }
        }
        #pragma unroll
        for (int pp = 0; pp < 4; pp++)
            #pragma unroll
            for (int jj = 0; jj < 8; jj++) {
                int j = lane + 32 * jj;
                float zlo, zhi;
                unpack2(acc2[pp][jj], zlo, zhi);
                float wv3 = w3s[j];
                dz2u[(4 * w + pp) * 256 + j] =
                    pack2(zlo > 0.0f ? wv3 : 0.0f, zhi > 0.0f ? wv3 : 0.0f);
            }
    }

    // ---- phase 3: dh1 = dz2 @ W2^T ; dz1 = dh1 * (h1>0) ; score = dz1 @ W1a^T ----
    {
        unsigned long long acc2[4][8];
        #pragma unroll
        for (int pp = 0; pp < 4; pp++)
            #pragma unroll
            for (int kk = 0; kk < 8; kk++) acc2[pp][kk] = 0ull;

        for (int c = 0; c < 16; c++) {
            __syncthreads();   // protects wtd reuse across phases/chunks
            #pragma unroll
            for (int q = 0; q < 16; q++) {
                float v = g_W2T[(c * 16 + q) * HH + t];
                wtdu[q * 256 + t] = pack2(v, v);
            }
            __syncthreads();
            #pragma unroll
            for (int jr = 0; jr < 16; jr++) {
                unsigned long long wv[8];
                #pragma unroll
                for (int kk = 0; kk < 8; kk++) wv[kk] = wtdu[jr * 256 + lane + 32 * kk];
                #pragma unroll
                for (int pp = 0; pp < 4; pp++) {
                    unsigned long long dzv = dz2u[(4 * w + pp) * 256 + c * 16 + jr];
                    #pragma unroll
                    for (int kk = 0; kk < 8; kk++)
                        acc2[pp][kk] = fma2(dzv, wv[kk], acc2[pp][kk]);
                }
            }
        }

        unsigned long long sacc[4][6];
        #pragma unroll
        for (int pp = 0; pp < 4; pp++)
            #pragma unroll
            for (int d = 0; d < 6; d++) sacc[pp][d] = 0ull;

        #pragma unroll
        for (int pp = 0; pp < 4; pp++) {
            #pragma unroll
            for (int kk = 0; kk < 8; kk++) {
                int k = lane + 32 * kk;
                float dlo, dhi, hlo, hhi;
                unpack2(acc2[pp][kk], dlo, dhi);
                unpack2(h1u[(4 * w + pp) * 256 + k], hlo, hhi);
                dlo = hlo > 0.0f ? dlo : 0.0f;
                dhi = hhi > 0.0f ? dhi : 0.0f;
                unsigned long long dz1 = pack2(dlo, dhi);
                #pragma unroll
                for (int d = 0; d < 6; d++)
                    sacc[pp][d] = fma2(dz1, w1au[d * 256 + k], sacc[pp][d]);
            }
        }

        float slo[24], shi[24];
        #pragma unroll
        for (int pp = 0; pp < 4; pp++)
            #pragma unroll
            for (int d = 0; d < 6; d++) unpack2(sacc[pp][d], slo[pp * 6 + d], shi[pp * 6 + d]);

        #pragma unroll
        for (int off = 16; off > 0; off >>= 1) {
            #pragma unroll
            for (int q = 0; q < 24; q++) {
                slo[q] += __shfl_xor_sync(0xffffffffu, slo[q], off);
                shi[q] += __shfl_xor_sync(0xffffffffu, shi[q], off);
            }
        }
        if (lane == 0) {
            #pragma unroll
            for (int pp = 0; pp < 4; pp++) {
                int r0 = R0 + 8 * w + 2 * pp;
                #pragma unroll
                for (int d = 0; d < 6; d++) {
                    g_score[r0 * DD + d]       = slo[pp * 6 + d];
                    g_score[(r0 + 1) * DD + d] = shi[pp * 6 + d];
                }
            }
        }
    }
}

// ---------------- SVGD / RBF update: one CTA (1024 thr) per batch ----------------
__global__ __launch_bounds__(1024)
void svgd_kernel() {
    const int b   = blockIdx.x;
    const int tid = threadIdx.x;
    const int i   = tid >> 5;     // particle i (warp)
    const int j   = tid & 31;     // particle j (lane)

    __shared__ float xsm[NN][DD];
    __shared__ float ssm[NN][DD];
    __shared__ float sd[NN * NN];

    if (tid < NN * DD) {
        xsm[tid / DD][tid % DD] = g_a[b * NN * DD + tid];
    } else if (tid < 2 * NN * DD) {
        int q = tid - NN * DD;
        ssm[q / DD][q % DD] = g_score[b * NN * DD + q];
    }
    __syncthreads();

    float diff[DD];
    float dsq = 0.0f;
    #pragma unroll
    for (int d = 0; d < DD; d++) {
        float df = xsm[i][d] - xsm[j][d];
        diff[d] = df;
        dsq += df * df;
    }
    sd[tid] = dsq;
    __syncthreads();

    // bitonic sort of 1024 distances (ascending), exact median semantics
    for (int k = 2; k <= 1024; k <<= 1) {
        for (int m = k >> 1; m > 0; m >>= 1) {
            int ixj = tid ^ m;
            if (ixj > tid) {
                float v0 = sd[tid], v1 = sd[ixj];
                bool asc = ((tid & k) == 0);
                bool swap = asc ? (v0 > v1) : (v0 < v1);
                if (swap) { sd[tid] = v1; sd[ixj] = v0; }
            }
            __syncthreads();
        }
    }
    float med = sd[(NN * NN - 1) / 2];   // index 511
    const float LOG_NP1 = 3.4965076f;    // float32(log(33))
    float h     = med / (2.0f * LOG_NP1);
    float gamma = 1.0f / (1e-8f + 2.0f * h);

    float Kv   = expf(-gamma * dsq);
    float coef = -2.0f * gamma * Kv;     // Kgrad_d = coef * diff_d

    float phi[DD];
    float l4 = 0.0f;
    #pragma unroll
    for (int d = 0; d < DD; d++) {
        float kg = coef * diff[d];
        float sv = ssm[j][d];
        phi[d] = Kv * sv - kg;           // K*s - Kgrad.sum contribution
        l4 += kg * sv;
    }
    float l5 = 2.0f * gamma * dsq * Kv - (float)DD * Kv;

    // reduce over j (lanes)
    #pragma unroll
    for (int off = 16; off > 0; off >>= 1) {
        #pragma unroll
        for (int d = 0; d < DD; d++)
            phi[d] += __shfl_xor_sync(0xffffffffu, phi[d], off);
        l4 += __shfl_xor_sync(0xffffffffu, l4, off);
        l5 += __shfl_xor_sync(0xffffffffu, l5, off);
    }

    if (j == 0) {
        int row = b * NN + i;
        #pragma unroll
        for (int d = 0; d < DD; d++) {
            float an = xsm[i][d] + 0.1f * (phi[d] * (1.0f / (float)NN));
            an = fminf(fmaxf(an, -1.0f), 1.0f);
            g_a[row * DD + d] = an;
        }
        float line4 = l4 * (1.0f / (float)NN);
        float line5 = -2.0f * gamma * (l5 * (1.0f / (float)NN));
        g_logp[row] = g_logp[row] - 0.1f * (line4 + line5);
    }
}

// ---------------- launcher ----------------
extern "C" void kernel_launch(void* const* d_in, const int* in_sizes, int n_in,
                              void* d_out, int out_size) {
    const float* obs = (const float*)d_in[0];
    const float* a   = (const float*)d_in[1];
    const float* W1  = (const float*)d_in[2];
    const float* b1  = (const float*)d_in[3];
    const float* W2  = (const float*)d_in[4];
    const float* b2  = (const float*)d_in[5];
    const float* W3  = (const float*)d_in[6];
    float* out = (float*)d_out;

    cudaFuncSetAttribute(mlp_score_kernel,
                         cudaFuncAttributeMaxDynamicSharedMemorySize, SMEM_BYTES);

    transpose_w2_kernel<<<HH, HH>>>(W2);
    init_kernel<<<(BN * DD + 255) / 256, 256>>>(a);

    for (int s = 0; s < NSTEPS; s++) {
        mlp_score_kernel<<<MLP_GRID, 256, SMEM_BYTES>>>(obs, W1, b1, W2, b2, W3);
        svgd_kernel<<<BB, 1024>>>();
    }

    int total = BN * DD + BN;  // a (393216) then logp (65536)
    int n = (out_size < total) ? out_size : total;
    writeout_kernel<<<(n + 255) / 256, 256>>>(out, n);
}